// round 1
// baseline (speedup 1.0000x reference)
#include <cuda_runtime.h>
#include <math.h>

#define NT 10
#define NL 16
#define NNODES 31
#define DD 256
#define BB 4096
#define NCOMBO 160          // NT * NL distinct (tree, leaf) sequences
#define NODES_TOT 310       // NT * NNODES distinct embedding nodes
#define G4 1024             // 4 * D gate width

// Static scratch (no allocations allowed)
__device__ __align__(16) float g_XG[NODES_TOT * G4];     // 1.27 MB
__device__ __align__(16) float g_H[2][NCOMBO * DD];      // ping-pong h
__device__ __align__(16) float g_C[2][NCOMBO * DD];      // ping-pong c

__device__ __forceinline__ float sigf(float x) { return 1.0f / (1.0f + __expf(-x)); }

// ---------------------------------------------------------------------------
// XG[n][j] = sum_d emb[n][d] * W_ih[j][d] + b_ih[j] + b_hh[j]
// M=310 (padded 320), N=1024, K=256. BM=32, BN=64, BK=64. grid(16,10), 256thr.
// ---------------------------------------------------------------------------
__global__ void xg_kernel(const float* __restrict__ emb,
                          const float* __restrict__ W_ih,
                          const float* __restrict__ b_ih,
                          const float* __restrict__ b_hh) {
    __shared__ float sE[32][65];
    __shared__ float sW[64][65];
    const int n0 = blockIdx.x * 64;
    const int m0 = blockIdx.y * 32;
    const int tid = threadIdx.x;
    const int tm = tid >> 4, tn = tid & 15;
    float acc[2][4] = {};

    for (int k0 = 0; k0 < 256; k0 += 64) {
        // E tile: 32x64 = 512 float4
        for (int i = tid; i < 512; i += 256) {
            int r = i >> 4, c4 = i & 15;
            int gm = m0 + r;
            float4 v = (gm < NODES_TOT)
                     ? *(const float4*)(emb + gm * 256 + k0 + c4 * 4)
                     : make_float4(0.f, 0.f, 0.f, 0.f);
            sE[r][c4*4+0] = v.x; sE[r][c4*4+1] = v.y;
            sE[r][c4*4+2] = v.z; sE[r][c4*4+3] = v.w;
        }
        // W tile: 64x64 = 1024 float4
        for (int i = tid; i < 1024; i += 256) {
            int r = i >> 4, c4 = i & 15;
            float4 v = *(const float4*)(W_ih + (n0 + r) * 256 + k0 + c4 * 4);
            sW[r][c4*4+0] = v.x; sW[r][c4*4+1] = v.y;
            sW[r][c4*4+2] = v.z; sW[r][c4*4+3] = v.w;
        }
        __syncthreads();
        #pragma unroll
        for (int k = 0; k < 64; ++k) {
            float e0 = sE[tm*2+0][k], e1 = sE[tm*2+1][k];
            float w0 = sW[tn*4+0][k], w1 = sW[tn*4+1][k];
            float w2 = sW[tn*4+2][k], w3 = sW[tn*4+3][k];
            acc[0][0] += e0*w0; acc[0][1] += e0*w1; acc[0][2] += e0*w2; acc[0][3] += e0*w3;
            acc[1][0] += e1*w0; acc[1][1] += e1*w1; acc[1][2] += e1*w2; acc[1][3] += e1*w3;
        }
        __syncthreads();
    }
    #pragma unroll
    for (int mm = 0; mm < 2; ++mm) {
        int m = m0 + tm*2 + mm;
        if (m >= NODES_TOT) continue;
        #pragma unroll
        for (int nn = 0; nn < 4; ++nn) {
            int n = n0 + tn*4 + nn;
            g_XG[m * G4 + n] = acc[mm][nn] + b_ih[n] + b_hh[n];
        }
    }
}

// ---------------------------------------------------------------------------
// Step 0: h0 = 0, so gates come straight from XG at the root node (tree*31).
// ---------------------------------------------------------------------------
__global__ void step0_kernel() {
    int idx = blockIdx.x * blockDim.x + threadIdx.x;   // 160*256 = 40960
    int combo = idx >> 8;
    int d = idx & 255;
    int tree = combo >> 4;
    const float* xg = g_XG + (tree * NNODES) * G4;
    float gi = xg[d], gg = xg[512 + d], go = xg[768 + d];
    float c = sigf(gi) * tanhf(gg);               // sig(f)*0 term vanishes
    float h = sigf(go) * tanhf(c);
    g_H[0][idx] = h;
    g_C[0][idx] = c;
}

// ---------------------------------------------------------------------------
// Steps 1..4: for each combo, gates = XG[node_t] + h_prev @ W_hh^T, then LSTM
// update. Block = 20 combos x 16 d's (64 gate-rows). grid(16,8)=128 blocks
// (single wave on 148 SMs), 320 threads (10 warps). Warp = 2 combos x 64
// rows; lane owns rows {lane, lane+32}. h reads are smem broadcasts, W reads
// are conflict-free (pitch 65). shfl_xor(16) reunites the 4 gates per (c,d).
// ---------------------------------------------------------------------------
__global__ __launch_bounds__(320) void step_kernel(int t, int bin, int bout,
                                                   const float* __restrict__ W_hh) {
    __shared__ __align__(16) float sh[20 * 256];   // h tile for 20 combos
    __shared__ float sW[64][65];                   // 64 gate rows x 64 k
    const int tid = threadIdx.x;
    const int dx = blockIdx.x;        // d-tile: d0 = dx*16
    const int cy = blockIdx.y;        // combo-tile: combos cy*20 .. cy*20+19
    const int d0 = dx << 4;
    const float* Hin = g_H[bin];
    const float* Cin = g_C[bin];

    // Load h tile (20x256 = 1280 float4), coalesced.
    {
        const float4* src = (const float4*)(Hin + cy * 20 * 256);
        float4* dst = (float4*)sh;
        for (int i = tid; i < 1280; i += 320) dst[i] = src[i];
    }

    const int w = tid >> 5, lane = tid & 31;
    const int lc0 = 2 * w, lc1 = lc0 + 1;          // local combos in tile
    const int c0 = cy * 20 + lc0, c1 = c0 + 1;
    const int ra = lane, rb = lane + 32;

    float a00 = 0.f, a01 = 0.f, a10 = 0.f, a11 = 0.f;
    const float4* sh4 = (const float4*)sh;

    for (int k0 = 0; k0 < 256; k0 += 64) {
        // Load W rows: row r -> gate=(r>>4), dl=(r&15), j = gate*256 + d0 + dl
        for (int i = tid; i < 64 * 16; i += 320) {
            int r = i >> 4, c4 = i & 15;
            int j = ((r >> 4) << 8) + d0 + (r & 15);
            float4 v = *(const float4*)(W_hh + j * 256 + k0 + c4 * 4);
            sW[r][c4*4+0] = v.x; sW[r][c4*4+1] = v.y;
            sW[r][c4*4+2] = v.z; sW[r][c4*4+3] = v.w;
        }
        __syncthreads();
        int kb = k0 >> 2;
        #pragma unroll
        for (int k4 = 0; k4 < 16; ++k4) {
            float4 h0 = sh4[lc0 * 64 + kb + k4];   // broadcast within warp
            float4 h1 = sh4[lc1 * 64 + kb + k4];
            float wa0 = sW[ra][k4*4+0], wa1 = sW[ra][k4*4+1];
            float wa2 = sW[ra][k4*4+2], wa3 = sW[ra][k4*4+3];
            float wb0 = sW[rb][k4*4+0], wb1 = sW[rb][k4*4+1];
            float wb2 = sW[rb][k4*4+2], wb3 = sW[rb][k4*4+3];
            a00 += h0.x*wa0; a00 += h0.y*wa1; a00 += h0.z*wa2; a00 += h0.w*wa3;
            a01 += h0.x*wb0; a01 += h0.y*wb1; a01 += h0.z*wb2; a01 += h0.w*wb3;
            a10 += h1.x*wa0; a10 += h1.y*wa1; a10 += h1.z*wa2; a10 += h1.w*wa3;
            a11 += h1.x*wb0; a11 += h1.y*wb1; a11 += h1.z*wb2; a11 += h1.w*wb3;
        }
        __syncthreads();
    }

    // Gate exchange: lane<16 holds (gate0, gate2) for both combos; lane>=16
    // holds (gate1, gate3). lane<16 finalizes c0; lane>=16 finalizes c1.
    float sA = (lane & 16) ? a00 : a10;
    float sB = (lane & 16) ? a01 : a11;
    float rA = __shfl_xor_sync(0xffffffffu, sA, 16);
    float rB = __shfl_xor_sync(0xffffffffu, sB, 16);

    float gi, gf, gg, go;
    int c;
    if (lane & 16) { c = c1; gi = rA;  gf = a10; gg = rB;  go = a11; }
    else           { c = c0; gi = a00; gf = rA;  gg = a01; go = rB;  }

    int dl = lane & 15;
    int d = d0 + dl;
    int tree = c >> 4, leaf = c & 15;
    int local = ((1 << t) - 1) + (leaf >> (4 - t));   // heap-indexed path node
    const float* xg = g_XG + (tree * NNODES + local) * G4;
    gi += xg[d]; gf += xg[256 + d]; gg += xg[512 + d]; go += xg[768 + d];

    float cp = Cin[c * 256 + d];
    float cn = sigf(gf) * cp + sigf(gi) * tanhf(gg);
    float hn = sigf(go) * tanhf(cn);
    g_C[bout][c * 256 + d] = cn;
    g_H[bout][c * 256 + d] = hn;
}

// ---------------------------------------------------------------------------
// Gather: one warp per (b, tree). Argmax of the one-hot via ballot, then copy
// 256 floats (2 float4 per lane) from the 160-row H table (L2-resident).
// ---------------------------------------------------------------------------
__global__ void gather_kernel(const float* __restrict__ cross,
                              float* __restrict__ out) {
    int gw = (blockIdx.x * blockDim.x + threadIdx.x) >> 5;
    int lane = threadIdx.x & 31;
    if (gw >= BB * NT) return;
    int b = gw / NT;
    int tr = gw - b * NT;
    float v = 0.f;
    if (lane < NL) v = cross[b * (NT * NL) + tr * NL + lane];
    unsigned m = __ballot_sync(0xffffffffu, v > 0.5f);
    int leaf = __ffs(m) - 1;
    const float4* src = (const float4*)(g_H[0] + (tr * NL + leaf) * 256);
    float4* dst = (float4*)(out + (size_t)gw * 256);
    dst[lane]      = src[lane];
    dst[lane + 32] = src[lane + 32];
}

// ---------------------------------------------------------------------------
extern "C" void kernel_launch(void* const* d_in, const int* in_sizes, int n_in,
                              void* d_out, int out_size) {
    const float* cross = (const float*)d_in[0];
    const float* emb   = (const float*)d_in[1];
    const float* W_ih  = (const float*)d_in[2];
    const float* W_hh  = (const float*)d_in[3];
    const float* b_ih  = (const float*)d_in[4];
    const float* b_hh  = (const float*)d_in[5];
    float* out = (float*)d_out;

    xg_kernel<<<dim3(16, 10), 256>>>(emb, W_ih, b_ih, b_hh);
    step0_kernel<<<160, 256>>>();
    step_kernel<<<dim3(16, 8), 320>>>(1, 0, 1, W_hh);
    step_kernel<<<dim3(16, 8), 320>>>(2, 1, 0, W_hh);
    step_kernel<<<dim3(16, 8), 320>>>(3, 0, 1, W_hh);
    step_kernel<<<dim3(16, 8), 320>>>(4, 1, 0, W_hh);
    gather_kernel<<<(BB * NT * 32 + 255) / 256, 256>>>(cross, out);
}